// round 13
// baseline (speedup 1.0000x reference)
#include <cuda_runtime.h>
#include <cuda_bf16.h>
#include <cstdint>
#include <math.h>

#define BM 128
#define NTHREADS 256

// BK=64 staged kernels (proj + head): stage = (128+128) rows * 144B
#define ROWH 144
#define H2_STAGE 36864
#define H2_BIAS 110592
#define H2_TGT  111104
#define H2_SMEM 111616
#define PROJ_SMEM 110592

// merged tails smem = max over phases (tail1: 128*528 + 3*128*80 + 2048)
#define TAILS_SMEM 100352

// ---------------- static scratch ----------------
__device__ __align__(16) __nv_bfloat16 g_hidden[1024 * 1024];
__device__ __align__(16) __nv_bfloat16 g_pT[1360 * 1024];     // [1360][1024]
__device__ __align__(16) __nv_bfloat16 g_proj[1024 * 1360];   // [1024][1360]
__device__ __align__(16) __nv_bfloat16 g_Wb[36923808];
__device__ float g_biasHead[20000];
__device__ float g_sumExp[4 * 1024];
__device__ float g_tgtLogit[1024];
__device__ float g_clLogit[1024 * 3];
__device__ int   g_target[1024];

// ---------------- target decode ----------------
__global__ void decode_targets_kernel(const void* __restrict__ tptr, int n) {
    __shared__ int bad;
    if (threadIdx.x == 0) bad = 0;
    __syncthreads();
    const long long* t64 = (const long long*)tptr;
    int lim = (n < 512) ? n : 512;
    for (int i = threadIdx.x; i < lim; i += blockDim.x) {
        long long v = t64[i];
        if (v < 0 || v >= 267735) atomicExch(&bad, 1);
    }
    __syncthreads();
    int is64 = !bad;
    for (int i = threadIdx.x; i < n; i += blockDim.x)
        g_target[i] = is64 ? (int)t64[i] : ((const int*)tptr)[i];
}

// ---------------- prep_light ----------------
__global__ void prep_light_kernel(const float* __restrict__ hidden,
                                  const float* __restrict__ p0, const float* __restrict__ p1,
                                  const float* __restrict__ p2, const float* __restrict__ p3) {
    const int U_H  = 262144;
    const int U_PT = 1392640;
    const int U_Z  = 8192;
    const int TOTAL = U_H + U_PT + U_Z;
    int idx = blockIdx.x * blockDim.x + threadIdx.x;
    int stride = gridDim.x * blockDim.x;
    for (int u = idx; u < TOTAL; u += stride) {
        if (u < U_H) {
            int e = u * 4;
            float4 f = *reinterpret_cast<const float4*>(hidden + e);
            __nv_bfloat162 lo = __floats2bfloat162_rn(f.x, f.y);
            __nv_bfloat162 hi = __floats2bfloat162_rn(f.z, f.w);
            *reinterpret_cast<uint2*>(g_hidden + e) = make_uint2(*(uint32_t*)&lo, *(uint32_t*)&hi);
        } else if (u < U_H + U_PT) {
            int j = u - U_H;
            const float* p; int E; int base;
            if (j < 1024 * 1024)      { p = p0; E = 1024; base = 0; }
            else if (j < 1280 * 1024) { p = p1; E = 256;  base = 1024 * 1024; }
            else if (j < 1344 * 1024) { p = p2; E = 64;   base = 1280 * 1024; }
            else                      { p = p3; E = 16;   base = 1344 * 1024; }
            int loc = j - base;
            int e = loc >> 10;
            int k = loc & 1023;
            g_pT[j] = __float2bfloat16(p[k * E + e]);
        } else {
            int j = u - U_H - U_PT;
            if (j < 4096)      g_sumExp[j] = 0.f;
            else if (j < 5120) g_tgtLogit[j - 4096] = 0.f;
            else               g_clLogit[j - 5120] = 0.f;
        }
    }
}

// ---------------- prep_W head part ----------------
__global__ void prep_w_head_kernel(const float* __restrict__ W0, const float* __restrict__ cw,
                                   const float* __restrict__ b0, const float* __restrict__ cb) {
    const int U_W = 5120000;
    const int U_B = 20000;
    const int TOTAL = U_W + U_B;
    int idx = blockIdx.x * blockDim.x + threadIdx.x;
    int stride = gridDim.x * blockDim.x;
    for (int u = idx; u < TOTAL; u += stride) {
        if (u < U_W) {
            int e = u * 4;
            const float* src = (e < 20476928) ? W0 + e : cw + (e - 20476928);
            float4 f = *reinterpret_cast<const float4*>(src);
            __nv_bfloat162 lo = __floats2bfloat162_rn(f.x, f.y);
            __nv_bfloat162 hi = __floats2bfloat162_rn(f.z, f.w);
            *reinterpret_cast<uint2*>(g_Wb + e) = make_uint2(*(uint32_t*)&lo, *(uint32_t*)&hi);
        } else {
            int j = u - U_W;
            g_biasHead[j] = (j < 19997) ? b0[j] : cb[j - 19997];
        }
    }
}

// ---------------- prep_W tail part ----------------
__global__ void prep_w_tail_kernel(const float* __restrict__ W1, const float* __restrict__ W2,
                                   const float* __restrict__ W3) {
    const int TOTAL = 4110952;
    int idx = blockIdx.x * blockDim.x + threadIdx.x;
    int stride = gridDim.x * blockDim.x;
    for (int u = idx; u < TOTAL; u += stride) {
        int e = 20480000 + u * 4;
        const float* src;
        if (e < 25600000)       src = W1 + (e - 20480000);
        else if (e < 35840000)  src = W2 + (e - 25600000);
        else                    src = W3 + (e - 35840000);
        float4 f = *reinterpret_cast<const float4*>(src);
        __nv_bfloat162 lo = __floats2bfloat162_rn(f.x, f.y);
        __nv_bfloat162 hi = __floats2bfloat162_rn(f.z, f.w);
        *reinterpret_cast<uint2*>(g_Wb + e) = make_uint2(*(uint32_t*)&lo, *(uint32_t*)&hi);
    }
}

// ---------------- asm helpers ----------------
__device__ __forceinline__ void cpa16(uint32_t dst, const void* src, int bytes) {
    asm volatile("cp.async.cg.shared.global [%0], [%1], 16, %2;\n"
                 :: "r"(dst), "l"(src), "r"(bytes));
}
__device__ __forceinline__ void ldsm4(uint32_t& r0, uint32_t& r1, uint32_t& r2, uint32_t& r3,
                                      uint32_t addr) {
    asm volatile("ldmatrix.sync.aligned.m8n8.x4.shared.b16 {%0,%1,%2,%3}, [%4];"
                 : "=r"(r0), "=r"(r1), "=r"(r2), "=r"(r3) : "r"(addr));
}
__device__ __forceinline__ void mma16816(float c[4], const uint32_t a[4], const uint32_t b0,
                                         const uint32_t b1) {
    asm volatile(
        "mma.sync.aligned.m16n8k16.row.col.f32.bf16.bf16.f32 "
        "{%0,%1,%2,%3}, {%4,%5,%6,%7}, {%8,%9}, {%0,%1,%2,%3};\n"
        : "+f"(c[0]), "+f"(c[1]), "+f"(c[2]), "+f"(c[3])
        : "r"(a[0]), "r"(a[1]), "r"(a[2]), "r"(a[3]), "r"(b0), "r"(b1));
}

// ================= projection GEMM (K=1024, BK=64 staging) =================
__global__ __launch_bounds__(NTHREADS, 2)
void proj_kernel(const __nv_bfloat16* __restrict__ A, const __nv_bfloat16* __restrict__ B,
                 int Nn, __nv_bfloat16* __restrict__ Cout, int ldc) {
    const int K = 1024;
    extern __shared__ __align__(16) char smem[];
    uint32_t sbase = (uint32_t)__cvta_generic_to_shared(smem);

    const int tid = threadIdx.x;
    const int lane = tid & 31, wid = tid >> 5;
    const int gid = lane >> 2, tg = lane & 3;
    const int warp_m = wid >> 1, warp_n = wid & 1;
    const int m0 = blockIdx.x * BM;
    const int n0 = blockIdx.y * 128;

    const int ntiles = 16;

    auto issue = [&](int kt, int sb) {
        int k0 = kt * 64;
        uint32_t sA = sbase + (uint32_t)sb * H2_STAGE;
        uint32_t sB = sA + BM * ROWH;
#pragma unroll
        for (int i = 0; i < 4; ++i) {
            int t = tid + i * NTHREADS;
            int row = t >> 3, ch = t & 7;
            int kg = k0 + ch * 8;
            cpa16(sA + row * ROWH + ch * 16, A + (size_t)(m0 + row) * K + kg, 16);
        }
#pragma unroll
        for (int i = 0; i < 4; ++i) {
            int t = tid + i * NTHREADS;
            int row = t >> 3, ch = t & 7;
            int kg = k0 + ch * 8;
            int vg = n0 + row;
            bool ok = (vg < Nn);
            cpa16(sB + row * ROWH + ch * 16, B + (size_t)(ok ? vg : 0) * K + kg, ok ? 16 : 0);
        }
    };

    const int li = lane & 7, lq = lane >> 3;
    uint32_t aAddr[2], bAddr[4];
#pragma unroll
    for (int mt = 0; mt < 2; ++mt) {
        int row = warp_m * 32 + mt * 16 + (lq & 1) * 8 + li;
        aAddr[mt] = sbase + row * ROWH + ((lq >> 1) * 8) * 2;
    }
#pragma unroll
    for (int np = 0; np < 4; ++np) {
        int row = warp_n * 64 + np * 16 + (lq >> 1) * 8 + li;
        bAddr[np] = sbase + BM * ROWH + row * ROWH + ((lq & 1) * 8) * 2;
    }

    float c[2][8][4];
#pragma unroll
    for (int mt = 0; mt < 2; ++mt)
#pragma unroll
        for (int nt = 0; nt < 8; ++nt)
#pragma unroll
            for (int j = 0; j < 4; ++j) c[mt][nt][j] = 0.f;

    issue(0, 0);
    asm volatile("cp.async.commit_group;\n");
    issue(1, 1);
    asm volatile("cp.async.commit_group;\n");

    int sIssue = 2, sComp = 0;
    for (int it = 0; it < ntiles; ++it) {
        asm volatile("cp.async.wait_group 1;\n");
        __syncthreads();
        int nt_tile = it + 2;
        if (nt_tile < ntiles) issue(nt_tile, sIssue);
        sIssue = (sIssue == 2) ? 0 : sIssue + 1;
        asm volatile("cp.async.commit_group;\n");

        uint32_t so = (uint32_t)sComp * H2_STAGE;
        sComp = (sComp == 2) ? 0 : sComp + 1;
#pragma unroll
        for (int kk = 0; kk < 4; ++kk) {
            uint32_t a[2][4], b[4][4];
            ldsm4(a[0][0], a[0][1], a[0][2], a[0][3], aAddr[0] + so + kk * 32);
            ldsm4(a[1][0], a[1][1], a[1][2], a[1][3], aAddr[1] + so + kk * 32);
#pragma unroll
            for (int np = 0; np < 4; ++np)
                ldsm4(b[np][0], b[np][1], b[np][2], b[np][3], bAddr[np] + so + kk * 32);
#pragma unroll
            for (int mt = 0; mt < 2; ++mt)
#pragma unroll
                for (int nt = 0; nt < 8; ++nt)
                    mma16816(c[mt][nt], a[mt], b[nt >> 1][(nt & 1) * 2],
                             b[nt >> 1][(nt & 1) * 2 + 1]);
        }
    }

#pragma unroll
    for (int mt = 0; mt < 2; ++mt)
#pragma unroll
        for (int nt = 0; nt < 8; ++nt)
#pragma unroll
            for (int j2 = 0; j2 < 2; ++j2) {
                int row = m0 + warp_m * 32 + mt * 16 + gid + j2 * 8;
                int col = n0 + warp_n * 64 + nt * 8 + tg * 2;
                if (col + 1 < Nn) {
                    __nv_bfloat162 v = __floats2bfloat162_rn(c[mt][nt][j2 * 2],
                                                             c[mt][nt][j2 * 2 + 1]);
                    *reinterpret_cast<__nv_bfloat162*>(Cout + (size_t)row * ldc + col) = v;
                } else if (col < Nn) {
                    Cout[(size_t)row * ldc + col] = __float2bfloat16(c[mt][nt][j2 * 2]);
                }
            }
}

// ================= persistent head logits GEMM (K=1024, BK=64, grid=296) =================
#define HEAD_JOBS 1256
#define HEAD_GRID 296
__global__ __launch_bounds__(NTHREADS, 2)
void head_kernel(const float* __restrict__ bias) {
    const int K = 1024, Nn = 20000, lda = 1360;
    extern __shared__ __align__(16) char smem[];
    uint32_t sbase = (uint32_t)__cvta_generic_to_shared(smem);
    float* sBias = (float*)(smem + H2_BIAS);
    int*   sTgt  = (int*)(smem + H2_TGT);

    const int tid = threadIdx.x;
    const int lane = tid & 31, wid = tid >> 5;
    const int gid = lane >> 2, tg = lane & 3;
    const int warp_m = wid >> 1, warp_n = wid & 1;

    const __nv_bfloat16* A = g_proj;
    const __nv_bfloat16* B = g_Wb;
    const int ntiles = 16;

    const int li = lane & 7, lq = lane >> 3;
    uint32_t aAddr[2], bAddr[4];
#pragma unroll
    for (int mt = 0; mt < 2; ++mt) {
        int row = warp_m * 32 + mt * 16 + (lq & 1) * 8 + li;
        aAddr[mt] = sbase + row * ROWH + ((lq >> 1) * 8) * 2;
    }
#pragma unroll
    for (int np = 0; np < 4; ++np) {
        int row = warp_n * 64 + np * 16 + (lq >> 1) * 8 + li;
        bAddr[np] = sbase + BM * ROWH + row * ROWH + ((lq & 1) * 8) * 2;
    }

    for (int job = blockIdx.x; job < HEAD_JOBS; job += HEAD_GRID) {
        const int m0 = (job & 7) * BM;
        const int n0 = (job >> 3) * 128;

        __syncthreads();
        if (tid < 128) { int vg = n0 + tid; sBias[tid] = (vg < Nn) ? bias[vg] : 0.f; }
        if (tid < BM) sTgt[tid] = g_target[m0 + tid];

        auto issue = [&](int kt, int sb) {
            int k0 = kt * 64;
            uint32_t sA = sbase + (uint32_t)sb * H2_STAGE;
            uint32_t sB = sA + BM * ROWH;
#pragma unroll
            for (int i = 0; i < 4; ++i) {
                int t = tid + i * NTHREADS;
                int row = t >> 3, ch = t & 7;
                int kg = k0 + ch * 8;
                cpa16(sA + row * ROWH + ch * 16, A + (size_t)(m0 + row) * lda + kg, 16);
            }
#pragma unroll
            for (int i = 0; i < 4; ++i) {
                int t = tid + i * NTHREADS;
                int row = t >> 3, ch = t & 7;
                int kg = k0 + ch * 8;
                int vg = n0 + row;
                bool ok = (vg < Nn);
                cpa16(sB + row * ROWH + ch * 16, B + (size_t)(ok ? vg : 0) * K + kg, ok ? 16 : 0);
            }
        };

        float c[2][8][4];
#pragma unroll
        for (int mt = 0; mt < 2; ++mt)
#pragma unroll
            for (int nt = 0; nt < 8; ++nt)
#pragma unroll
                for (int j = 0; j < 4; ++j) c[mt][nt][j] = 0.f;

        issue(0, 0);
        asm volatile("cp.async.commit_group;\n");
        issue(1, 1);
        asm volatile("cp.async.commit_group;\n");

        int sIssue = 2, sComp = 0;
        for (int it = 0; it < ntiles; ++it) {
            asm volatile("cp.async.wait_group 1;\n");
            __syncthreads();
            int nt_tile = it + 2;
            if (nt_tile < ntiles) issue(nt_tile, sIssue);
            sIssue = (sIssue == 2) ? 0 : sIssue + 1;
            asm volatile("cp.async.commit_group;\n");

            uint32_t so = (uint32_t)sComp * H2_STAGE;
            sComp = (sComp == 2) ? 0 : sComp + 1;
#pragma unroll
            for (int kk = 0; kk < 4; ++kk) {
                uint32_t a[2][4], b[4][4];
                ldsm4(a[0][0], a[0][1], a[0][2], a[0][3], aAddr[0] + so + kk * 32);
                ldsm4(a[1][0], a[1][1], a[1][2], a[1][3], aAddr[1] + so + kk * 32);
#pragma unroll
                for (int np = 0; np < 4; ++np)
                    ldsm4(b[np][0], b[np][1], b[np][2], b[np][3], bAddr[np] + so + kk * 32);
#pragma unroll
                for (int mt = 0; mt < 2; ++mt)
#pragma unroll
                    for (int nt = 0; nt < 8; ++nt)
                        mma16816(c[mt][nt], a[mt], b[nt >> 1][(nt & 1) * 2],
                                 b[nt >> 1][(nt & 1) * 2 + 1]);
            }
        }

        const bool edge = (n0 + 128 > Nn);
#pragma unroll
        for (int mt = 0; mt < 2; ++mt) {
#pragma unroll
            for (int half = 0; half < 2; ++half) {
                int rloc = warp_m * 32 + mt * 16 + gid + half * 8;
                int row = m0 + rloc;
                int tv = sTgt[rloc];
                int tcol = (tv < 19997) ? tv - n0 : -1000000;
                float s2 = 0.f;
#pragma unroll
                for (int nt = 0; nt < 8; ++nt) {
#pragma unroll
                    for (int jj = 0; jj < 2; ++jj) {
                        int nloc = warp_n * 64 + nt * 8 + tg * 2 + jj;
                        float logit = c[mt][nt][half * 2 + jj] + sBias[nloc];
                        bool valid = !edge || (n0 + nloc < Nn);
                        if (valid) {
                            s2 += __expf(logit);
                            if (nloc == tcol) g_tgtLogit[row] = logit;
                            if (n0 + nloc >= Nn - 3)
                                g_clLogit[row * 3 + (n0 + nloc - (Nn - 3))] = logit;
                        }
                    }
                }
                s2 += __shfl_xor_sync(0xffffffffu, s2, 1);
                s2 += __shfl_xor_sync(0xffffffffu, s2, 2);
                if (tg == 0) atomicAdd(&g_sumExp[row], s2);
            }
        }
    }
}

// ================= tail body (templated device function) =================
template <int KV, int TPC, int CB>
__device__ __forceinline__
void tail_body(const float* __restrict__ bias, int Koff, int Boff, int Nn,
               int ytiles, int cut_l, float* __restrict__ sumExp, int ty) {
    constexpr int K_pad = (KV < 32) ? 32 : KV;
    constexpr int CH    = K_pad / 8;
    constexpr int ROWA  = K_pad * 2 + 16;
    constexpr int CEFF  = (KV < CB) ? KV : CB;
    constexpr int CKS   = CEFF / 16;
    constexpr int NT_K  = (KV > CB) ? KV / CB : 1;
    constexpr int ROWBT = CB * 2 + 16;
    constexpr int BSTG  = 128 * ROWBT;
    constexpr bool AREG = (KV <= 64);
    constexpr int NKS   = KV / 16;
    constexpr int BOFF  = BM * ROWA;
    constexpr int BIASOFF = BOFF + 3 * BSTG;
    constexpr int TGTOFF  = BIASOFF + 3 * 512;
    constexpr int CPR   = CB / 8;
    constexpr int RPP   = NTHREADS / CPR;
    constexpr int NPASS = 128 / RPP;

    extern __shared__ __align__(16) char smem[];
    uint32_t sbase = (uint32_t)__cvta_generic_to_shared(smem);
    int* sTgt = (int*)(smem + TGTOFF);

    const int tid = threadIdx.x;
    const int lane = tid & 31, wid = tid >> 5;
    const int gid = lane >> 2, tg = lane & 3;
    const int warp_m = wid >> 1, warp_n = wid & 1;
    const int m0 = blockIdx.x * BM;
    const int t0 = ty * TPC;
    const int ntl = (ytiles - t0 < TPC) ? (ytiles - t0) : TPC;
    const int QTOT = ntl * NT_K;

    const __nv_bfloat16* A = g_proj + Koff;
    const __nv_bfloat16* B = g_Wb + Boff;
    const int lda = 1360;

    if (tid < BM) sTgt[tid] = g_target[m0 + tid];

    for (int i = tid; i < BM * CH; i += NTHREADS) {
        int row = i / CH, ch = i - row * CH;
        int kg = ch * 8;
        cpa16(sbase + row * ROWA + ch * 16, A + (size_t)(m0 + row) * lda + kg,
              (kg < KV) ? 16 : 0);
    }
    asm volatile("cp.async.commit_group;\n");

    const int chB = tid % CPR;
    const int rB0 = tid / CPR;

    auto issueB = [&](int q, int sb) {
        int tile = q / NT_K;
        int kt = q - tile * NT_K;
        int n0 = (t0 + tile) * 128;
        int kg = kt * CB + chB * 8;
        uint32_t sB = sbase + BOFF + (uint32_t)sb * BSTG;
#pragma unroll
        for (int it = 0; it < NPASS; ++it) {
            int row = rB0 + it * RPP;
            int vg = n0 + row;
            bool ok = (vg < Nn) && (kg < KV);
            cpa16(sB + row * ROWBT + chB * 16, B + (size_t)(ok ? vg : 0) * KV + (ok ? kg : 0),
                  ok ? 16 : 0);
        }
        if (kt == 0 && tid < 32) {
            int off = n0 + tid * 4;
            int rem = Nn - off;
            int bytes = (rem >= 4) ? 16 : ((rem > 0) ? rem * 4 : 0);
            cpa16(sbase + BIASOFF + sb * 512 + tid * 16,
                  bias + ((rem > 0) ? off : 0), bytes);
        }
    };

    issueB(0, 0);
    asm volatile("cp.async.commit_group;\n");
    if (1 < QTOT) issueB(1, 1);
    asm volatile("cp.async.commit_group;\n");

    const int li = lane & 7, lq = lane >> 3;
    uint32_t aAddr[2], bOffu[4];
#pragma unroll
    for (int mt = 0; mt < 2; ++mt) {
        int row = warp_m * 32 + mt * 16 + (lq & 1) * 8 + li;
        aAddr[mt] = sbase + row * ROWA + ((lq >> 1) * 8) * 2;
    }
#pragma unroll
    for (int np = 0; np < 4; ++np) {
        int row = warp_n * 64 + np * 16 + (lq >> 1) * 8 + li;
        bOffu[np] = sbase + BOFF + row * ROWBT + ((lq & 1) * 8) * 2;
    }

    asm volatile("cp.async.wait_group 2;\n");
    __syncthreads();

    uint32_t aF[2][AREG ? NKS : 1][4];
    if constexpr (AREG) {
#pragma unroll
        for (int ks = 0; ks < NKS; ++ks) {
            ldsm4(aF[0][ks][0], aF[0][ks][1], aF[0][ks][2], aF[0][ks][3], aAddr[0] + ks * 32);
            ldsm4(aF[1][ks][0], aF[1][ks][1], aF[1][ks][2], aF[1][ks][3], aAddr[1] + ks * 32);
        }
    }

    float c[2][8][4];
#pragma unroll
    for (int mt = 0; mt < 2; ++mt)
#pragma unroll
        for (int nt = 0; nt < 8; ++nt)
#pragma unroll
            for (int j = 0; j < 4; ++j) c[mt][nt][j] = 0.f;

    int sIssue = 2, sComp = 0, sBiasStage = 0;
    int kt = 0, tile = 0;
    for (int q = 0; q < QTOT; ++q) {
        asm volatile("cp.async.wait_group 1;\n");
        __syncthreads();
        if (q + 2 < QTOT) issueB(q + 2, sIssue);
        sIssue = (sIssue == 2) ? 0 : sIssue + 1;
        asm volatile("cp.async.commit_group;\n");

#pragma unroll
        for (int kk = 0; kk < CKS; ++kk) {
            uint32_t b[4][4];
#pragma unroll
            for (int np = 0; np < 4; ++np)
                ldsm4(b[np][0], b[np][1], b[np][2], b[np][3],
                      bOffu[np] + (uint32_t)sComp * BSTG + kk * 32);
            const uint32_t* a0;
            const uint32_t* a1;
            uint32_t at[2][4];
            if constexpr (AREG) {
                a0 = aF[0][kt * CKS + kk];
                a1 = aF[1][kt * CKS + kk];
            } else {
                ldsm4(at[0][0], at[0][1], at[0][2], at[0][3], aAddr[0] + (kt * CKS + kk) * 32);
                ldsm4(at[1][0], at[1][1], at[1][2], at[1][3], aAddr[1] + (kt * CKS + kk) * 32);
                a0 = at[0]; a1 = at[1];
            }
#pragma unroll
            for (int nt = 0; nt < 8; ++nt) {
                mma16816(c[0][nt], a0, b[nt >> 1][(nt & 1) * 2], b[nt >> 1][(nt & 1) * 2 + 1]);
                mma16816(c[1][nt], a1, b[nt >> 1][(nt & 1) * 2], b[nt >> 1][(nt & 1) * 2 + 1]);
            }
        }
        sComp = (sComp == 2) ? 0 : sComp + 1;

        if (++kt == NT_K) {
            kt = 0;
            int n0 = (t0 + tile) * 128;
            const float* sBias = (const float*)(smem + BIASOFF + sBiasStage * 512);
            const bool edge = (n0 + 128 > Nn);
#pragma unroll
            for (int mt = 0; mt < 2; ++mt) {
#pragma unroll
                for (int half = 0; half < 2; ++half) {
                    int rloc = warp_m * 32 + mt * 16 + gid + half * 8;
                    int row = m0 + rloc;
                    int tcol = sTgt[rloc] - cut_l - n0;
                    float s2 = 0.f;
#pragma unroll
                    for (int nt = 0; nt < 8; ++nt) {
#pragma unroll
                        for (int jj = 0; jj < 2; ++jj) {
                            int nloc = warp_n * 64 + nt * 8 + tg * 2 + jj;
                            float logit = c[mt][nt][half * 2 + jj] + sBias[nloc];
                            bool valid = !edge || (n0 + nloc < Nn);
                            if (valid) {
                                s2 += __expf(logit);
                                if (nloc == tcol) g_tgtLogit[row] = logit;
                            }
                        }
                    }
                    s2 += __shfl_xor_sync(0xffffffffu, s2, 1);
                    s2 += __shfl_xor_sync(0xffffffffu, s2, 2);
                    if (tg == 0) atomicAdd(&sumExp[row], s2);
                }
            }
#pragma unroll
            for (int mt = 0; mt < 2; ++mt)
#pragma unroll
                for (int nt = 0; nt < 8; ++nt)
#pragma unroll
                    for (int j = 0; j < 4; ++j) c[mt][nt][j] = 0.f;
            ++tile;
            int qn = q + 1;
            sBiasStage = qn - (qn / 3) * 3;
        }
    }
}

// ================= merged tails kernel (ordered phases: tail2 | tail3 | tail1) ========
__global__ __launch_bounds__(NTHREADS, 2)
void tails_kernel(const float* __restrict__ b1, const float* __restrict__ b2,
                  const float* __restrict__ b3, float* __restrict__ dsum) {
    int y = blockIdx.y;
    if (y < 74) {
        tail_body<64, 17, 64>(b2, 1280, 25600000, 160000, 1250, 39997, dsum + 2048, y);
    } else if (y < 108) {
        tail_body<16, 16, 32>(b3, 1344, 35840000, 67738, 530, 199997, dsum + 3072, y - 74);
    } else {
        tail_body<256, 5, 32>(b1, 1024, 20480000, 20000, 157, 19997, dsum + 1024, y - 108);
    }
}

// ---------------- final NLL ----------------
__global__ void final_kernel(float* __restrict__ out) {
    int n = blockIdx.x * blockDim.x + threadIdx.x;
    if (n >= 1024) return;
    int t = g_target[n];
    int c = (t < 19997) ? 0 : (t < 39997) ? 1 : (t < 199997) ? 2 : 3;
    float head_lse = logf(g_sumExp[n]);
    float nll;
    if (c == 0) {
        nll = head_lse - g_tgtLogit[n];
    } else {
        float tail_lse = logf(g_sumExp[c * 1024 + n]);
        nll = head_lse - g_clLogit[n * 3 + (c - 1)] + tail_lse - g_tgtLogit[n];
    }
    out[n] = nll;
}

// ---------------- launch ----------------
extern "C" void kernel_launch(void* const* d_in, const int* in_sizes, int n_in,
                              void* d_out, int out_size) {
    const float* hidden = (const float*)d_in[0];
    const void*  target = (const void*)d_in[1];
    const float* W0 = (const float*)d_in[2];
    const float* b0 = (const float*)d_in[3];
    const float* p0 = (const float*)d_in[4];
    const float* W1 = (const float*)d_in[5];
    const float* b1 = (const float*)d_in[6];
    const float* p1 = (const float*)d_in[7];
    const float* W2 = (const float*)d_in[8];
    const float* b2 = (const float*)d_in[9];
    const float* p2 = (const float*)d_in[10];
    const float* W3 = (const float*)d_in[11];
    const float* b3 = (const float*)d_in[12];
    const float* p3 = (const float*)d_in[13];
    const float* cw = (const float*)d_in[14];
    const float* cb = (const float*)d_in[15];
    float* out = (float*)d_out;

    static cudaStream_t s1 = nullptr;
    static cudaEvent_t r0, eWH, eW;
    if (!s1) {
        cudaStreamCreateWithFlags(&s1, cudaStreamNonBlocking);
        cudaEventCreateWithFlags(&r0, cudaEventDisableTiming);
        cudaEventCreateWithFlags(&eWH, cudaEventDisableTiming);
        cudaEventCreateWithFlags(&eW, cudaEventDisableTiming);
        cudaFuncSetAttribute(proj_kernel, cudaFuncAttributeMaxDynamicSharedMemorySize, PROJ_SMEM);
        cudaFuncSetAttribute(head_kernel, cudaFuncAttributeMaxDynamicSharedMemorySize, H2_SMEM);
        cudaFuncSetAttribute(tails_kernel, cudaFuncAttributeMaxDynamicSharedMemorySize, TAILS_SMEM);
    }

    __nv_bfloat16 *dh, *dpT, *dproj;
    float *dsum, *dbh;
    cudaGetSymbolAddress((void**)&dh, g_hidden);
    cudaGetSymbolAddress((void**)&dpT, g_pT);
    cudaGetSymbolAddress((void**)&dproj, g_proj);
    cudaGetSymbolAddress((void**)&dsum, g_sumExp);
    cudaGetSymbolAddress((void**)&dbh, g_biasHead);

    // side stream: decode + head-W convert (eWH), then tail-W convert (eW)
    cudaEventRecord(r0, 0);
    cudaStreamWaitEvent(s1, r0, 0);
    decode_targets_kernel<<<1, 256, 0, s1>>>(target, 1024);
    prep_w_head_kernel<<<2048, 256, 0, s1>>>(W0, cw, b0, cb);
    cudaEventRecord(eWH, s1);
    prep_w_tail_kernel<<<2048, 256, 0, s1>>>(W1, W2, W3);
    cudaEventRecord(eW, s1);

    prep_light_kernel<<<1024, 256>>>(hidden, p0, p1, p2, p3);
    proj_kernel<<<dim3(8, 11), NTHREADS, PROJ_SMEM>>>(dh, dpT, 1360, dproj, 1360);

    // head starts as soon as W0 is converted; merged tails wait for the rest
    cudaStreamWaitEvent(0, eWH, 0);
    head_kernel<<<HEAD_GRID, NTHREADS, H2_SMEM>>>(dbh);
    cudaStreamWaitEvent(0, eW, 0);
    tails_kernel<<<dim3(8, 140), NTHREADS, TAILS_SMEM>>>(b1, b2, b3, dsum);

    final_kernel<<<4, 256>>>(out);
}

// round 14
// speedup vs baseline: 1.2794x; 1.2794x over previous
#include <cuda_runtime.h>
#include <cuda_bf16.h>
#include <cstdint>
#include <math.h>

#define BM 128
#define NTHREADS 256

// BK=64 staged kernels (proj + head): stage = (128+128) rows * 144B
#define ROWH 144
#define H2_STAGE 36864
#define H2_BIAS 110592
#define H2_TGT  111104
#define H2_SSUM 111616
#define H2_SMEM 112640
#define PROJ_SMEM 110592

// ---------------- static scratch ----------------
__device__ __align__(16) __nv_bfloat16 g_hidden[1024 * 1024];
__device__ __align__(16) __nv_bfloat16 g_pT[1360 * 1024];     // [1360][1024]
__device__ __align__(16) __nv_bfloat16 g_proj[1024 * 1360];   // [1024][1360]
__device__ __align__(16) __nv_bfloat16 g_Wb[36923808];
__device__ float g_biasHead[20000];
__device__ float g_sumExp[4 * 1024];
__device__ float g_tgtLogit[1024];
__device__ float g_clLogit[1024 * 3];
__device__ int   g_target[1024];

// ---------------- target decode ----------------
__global__ void decode_targets_kernel(const void* __restrict__ tptr, int n) {
    __shared__ int bad;
    if (threadIdx.x == 0) bad = 0;
    __syncthreads();
    const long long* t64 = (const long long*)tptr;
    int lim = (n < 512) ? n : 512;
    for (int i = threadIdx.x; i < lim; i += blockDim.x) {
        long long v = t64[i];
        if (v < 0 || v >= 267735) atomicExch(&bad, 1);
    }
    __syncthreads();
    int is64 = !bad;
    for (int i = threadIdx.x; i < n; i += blockDim.x)
        g_target[i] = is64 ? (int)t64[i] : ((const int*)tptr)[i];
}

// ---------------- prep_light ----------------
__global__ void prep_light_kernel(const float* __restrict__ hidden,
                                  const float* __restrict__ p0, const float* __restrict__ p1,
                                  const float* __restrict__ p2, const float* __restrict__ p3) {
    const int U_H  = 262144;
    const int U_PT = 1392640;
    const int U_Z  = 8192;
    const int TOTAL = U_H + U_PT + U_Z;
    int idx = blockIdx.x * blockDim.x + threadIdx.x;
    int stride = gridDim.x * blockDim.x;
    for (int u = idx; u < TOTAL; u += stride) {
        if (u < U_H) {
            int e = u * 4;
            float4 f = *reinterpret_cast<const float4*>(hidden + e);
            __nv_bfloat162 lo = __floats2bfloat162_rn(f.x, f.y);
            __nv_bfloat162 hi = __floats2bfloat162_rn(f.z, f.w);
            *reinterpret_cast<uint2*>(g_hidden + e) = make_uint2(*(uint32_t*)&lo, *(uint32_t*)&hi);
        } else if (u < U_H + U_PT) {
            int j = u - U_H;
            const float* p; int E; int base;
            if (j < 1024 * 1024)      { p = p0; E = 1024; base = 0; }
            else if (j < 1280 * 1024) { p = p1; E = 256;  base = 1024 * 1024; }
            else if (j < 1344 * 1024) { p = p2; E = 64;   base = 1280 * 1024; }
            else                      { p = p3; E = 16;   base = 1344 * 1024; }
            int loc = j - base;
            int e = loc >> 10;
            int k = loc & 1023;
            g_pT[j] = __float2bfloat16(p[k * E + e]);
        } else {
            int j = u - U_H - U_PT;
            if (j < 4096)      g_sumExp[j] = 0.f;
            else if (j < 5120) g_tgtLogit[j - 4096] = 0.f;
            else               g_clLogit[j - 5120] = 0.f;
        }
    }
}

// ---------------- prep_W head part ----------------
__global__ void prep_w_head_kernel(const float* __restrict__ W0, const float* __restrict__ cw,
                                   const float* __restrict__ b0, const float* __restrict__ cb) {
    const int U_W = 5120000;
    const int U_B = 20000;
    const int TOTAL = U_W + U_B;
    int idx = blockIdx.x * blockDim.x + threadIdx.x;
    int stride = gridDim.x * blockDim.x;
    for (int u = idx; u < TOTAL; u += stride) {
        if (u < U_W) {
            int e = u * 4;
            const float* src = (e < 20476928) ? W0 + e : cw + (e - 20476928);
            float4 f = *reinterpret_cast<const float4*>(src);
            __nv_bfloat162 lo = __floats2bfloat162_rn(f.x, f.y);
            __nv_bfloat162 hi = __floats2bfloat162_rn(f.z, f.w);
            *reinterpret_cast<uint2*>(g_Wb + e) = make_uint2(*(uint32_t*)&lo, *(uint32_t*)&hi);
        } else {
            int j = u - U_W;
            g_biasHead[j] = (j < 19997) ? b0[j] : cb[j - 19997];
        }
    }
}

// ---------------- prep_W tail part ----------------
__global__ void prep_w_tail_kernel(const float* __restrict__ W1, const float* __restrict__ W2,
                                   const float* __restrict__ W3) {
    const int TOTAL = 4110952;
    int idx = blockIdx.x * blockDim.x + threadIdx.x;
    int stride = gridDim.x * blockDim.x;
    for (int u = idx; u < TOTAL; u += stride) {
        int e = 20480000 + u * 4;
        const float* src;
        if (e < 25600000)       src = W1 + (e - 20480000);
        else if (e < 35840000)  src = W2 + (e - 25600000);
        else                    src = W3 + (e - 35840000);
        float4 f = *reinterpret_cast<const float4*>(src);
        __nv_bfloat162 lo = __floats2bfloat162_rn(f.x, f.y);
        __nv_bfloat162 hi = __floats2bfloat162_rn(f.z, f.w);
        *reinterpret_cast<uint2*>(g_Wb + e) = make_uint2(*(uint32_t*)&lo, *(uint32_t*)&hi);
    }
}

// ---------------- asm helpers ----------------
__device__ __forceinline__ void cpa16(uint32_t dst, const void* src, int bytes) {
    asm volatile("cp.async.cg.shared.global [%0], [%1], 16, %2;\n"
                 :: "r"(dst), "l"(src), "r"(bytes));
}
__device__ __forceinline__ void ldsm4(uint32_t& r0, uint32_t& r1, uint32_t& r2, uint32_t& r3,
                                      uint32_t addr) {
    asm volatile("ldmatrix.sync.aligned.m8n8.x4.shared.b16 {%0,%1,%2,%3}, [%4];"
                 : "=r"(r0), "=r"(r1), "=r"(r2), "=r"(r3) : "r"(addr));
}
__device__ __forceinline__ void mma16816(float c[4], const uint32_t a[4], const uint32_t b0,
                                         const uint32_t b1) {
    asm volatile(
        "mma.sync.aligned.m16n8k16.row.col.f32.bf16.bf16.f32 "
        "{%0,%1,%2,%3}, {%4,%5,%6,%7}, {%8,%9}, {%0,%1,%2,%3};\n"
        : "+f"(c[0]), "+f"(c[1]), "+f"(c[2]), "+f"(c[3])
        : "r"(a[0]), "r"(a[1]), "r"(a[2]), "r"(a[3]), "r"(b0), "r"(b1));
}

// ================= projection GEMM (K=1024, BK=64 staging) =================
__global__ __launch_bounds__(NTHREADS, 2)
void proj_kernel(const __nv_bfloat16* __restrict__ A, const __nv_bfloat16* __restrict__ B,
                 int Nn, __nv_bfloat16* __restrict__ Cout, int ldc) {
    const int K = 1024;
    extern __shared__ __align__(16) char smem[];
    uint32_t sbase = (uint32_t)__cvta_generic_to_shared(smem);

    const int tid = threadIdx.x;
    const int lane = tid & 31, wid = tid >> 5;
    const int gid = lane >> 2, tg = lane & 3;
    const int warp_m = wid >> 1, warp_n = wid & 1;
    const int m0 = blockIdx.x * BM;
    const int n0 = blockIdx.y * 128;

    const int ntiles = 16;

    auto issue = [&](int kt, int sb) {
        int k0 = kt * 64;
        uint32_t sA = sbase + (uint32_t)sb * H2_STAGE;
        uint32_t sB = sA + BM * ROWH;
#pragma unroll
        for (int i = 0; i < 4; ++i) {
            int t = tid + i * NTHREADS;
            int row = t >> 3, ch = t & 7;
            int kg = k0 + ch * 8;
            cpa16(sA + row * ROWH + ch * 16, A + (size_t)(m0 + row) * K + kg, 16);
        }
#pragma unroll
        for (int i = 0; i < 4; ++i) {
            int t = tid + i * NTHREADS;
            int row = t >> 3, ch = t & 7;
            int kg = k0 + ch * 8;
            int vg = n0 + row;
            bool ok = (vg < Nn);
            cpa16(sB + row * ROWH + ch * 16, B + (size_t)(ok ? vg : 0) * K + kg, ok ? 16 : 0);
        }
    };

    const int li = lane & 7, lq = lane >> 3;
    uint32_t aAddr[2], bAddr[4];
#pragma unroll
    for (int mt = 0; mt < 2; ++mt) {
        int row = warp_m * 32 + mt * 16 + (lq & 1) * 8 + li;
        aAddr[mt] = sbase + row * ROWH + ((lq >> 1) * 8) * 2;
    }
#pragma unroll
    for (int np = 0; np < 4; ++np) {
        int row = warp_n * 64 + np * 16 + (lq >> 1) * 8 + li;
        bAddr[np] = sbase + BM * ROWH + row * ROWH + ((lq & 1) * 8) * 2;
    }

    float c[2][8][4];
#pragma unroll
    for (int mt = 0; mt < 2; ++mt)
#pragma unroll
        for (int nt = 0; nt < 8; ++nt)
#pragma unroll
            for (int j = 0; j < 4; ++j) c[mt][nt][j] = 0.f;

    issue(0, 0);
    asm volatile("cp.async.commit_group;\n");
    issue(1, 1);
    asm volatile("cp.async.commit_group;\n");

    int sIssue = 2, sComp = 0;
    for (int it = 0; it < ntiles; ++it) {
        asm volatile("cp.async.wait_group 1;\n");
        __syncthreads();
        int nt_tile = it + 2;
        if (nt_tile < ntiles) issue(nt_tile, sIssue);
        sIssue = (sIssue == 2) ? 0 : sIssue + 1;
        asm volatile("cp.async.commit_group;\n");

        uint32_t so = (uint32_t)sComp * H2_STAGE;
        sComp = (sComp == 2) ? 0 : sComp + 1;
#pragma unroll
        for (int kk = 0; kk < 4; ++kk) {
            uint32_t a[2][4], b[4][4];
            ldsm4(a[0][0], a[0][1], a[0][2], a[0][3], aAddr[0] + so + kk * 32);
            ldsm4(a[1][0], a[1][1], a[1][2], a[1][3], aAddr[1] + so + kk * 32);
#pragma unroll
            for (int np = 0; np < 4; ++np)
                ldsm4(b[np][0], b[np][1], b[np][2], b[np][3], bAddr[np] + so + kk * 32);
#pragma unroll
            for (int mt = 0; mt < 2; ++mt)
#pragma unroll
                for (int nt = 0; nt < 8; ++nt)
                    mma16816(c[mt][nt], a[mt], b[nt >> 1][(nt & 1) * 2],
                             b[nt >> 1][(nt & 1) * 2 + 1]);
        }
    }

#pragma unroll
    for (int mt = 0; mt < 2; ++mt)
#pragma unroll
        for (int nt = 0; nt < 8; ++nt)
#pragma unroll
            for (int j2 = 0; j2 < 2; ++j2) {
                int row = m0 + warp_m * 32 + mt * 16 + gid + j2 * 8;
                int col = n0 + warp_n * 64 + nt * 8 + tg * 2;
                if (col + 1 < Nn) {
                    __nv_bfloat162 v = __floats2bfloat162_rn(c[mt][nt][j2 * 2],
                                                             c[mt][nt][j2 * 2 + 1]);
                    *reinterpret_cast<__nv_bfloat162*>(Cout + (size_t)row * ldc + col) = v;
                } else if (col < Nn) {
                    Cout[(size_t)row * ldc + col] = __float2bfloat16(c[mt][nt][j2 * 2]);
                }
            }
}

// ================= persistent head logits GEMM (K=1024, BK=64, grid=296) =================
#define HEAD_JOBS 1256
#define HEAD_GRID 296
__global__ __launch_bounds__(NTHREADS, 2)
void head_kernel(const float* __restrict__ bias) {
    const int K = 1024, Nn = 20000, lda = 1360;
    extern __shared__ __align__(16) char smem[];
    uint32_t sbase = (uint32_t)__cvta_generic_to_shared(smem);
    float* sBias = (float*)(smem + H2_BIAS);
    int*   sTgt  = (int*)(smem + H2_TGT);
    float* sSum  = (float*)(smem + H2_SSUM);   // [128][2]

    const int tid = threadIdx.x;
    const int lane = tid & 31, wid = tid >> 5;
    const int gid = lane >> 2, tg = lane & 3;
    const int warp_m = wid >> 1, warp_n = wid & 1;
    const int m0 = (blockIdx.x & 7) * BM;      // constant across this CTA's jobs

    const __nv_bfloat16* A = g_proj;
    const __nv_bfloat16* B = g_Wb;
    const int ntiles = 16;

    if (tid < 256) sSum[tid] = 0.f;
    if (tid < BM) sTgt[tid] = g_target[m0 + tid];

    const int li = lane & 7, lq = lane >> 3;
    uint32_t aAddr[2], bAddr[4];
#pragma unroll
    for (int mt = 0; mt < 2; ++mt) {
        int row = warp_m * 32 + mt * 16 + (lq & 1) * 8 + li;
        aAddr[mt] = sbase + row * ROWH + ((lq >> 1) * 8) * 2;
    }
#pragma unroll
    for (int np = 0; np < 4; ++np) {
        int row = warp_n * 64 + np * 16 + (lq >> 1) * 8 + li;
        bAddr[np] = sbase + BM * ROWH + row * ROWH + ((lq & 1) * 8) * 2;
    }

    for (int job = blockIdx.x; job < HEAD_JOBS; job += HEAD_GRID) {
        const int n0 = (job >> 3) * 128;

        __syncthreads();   // previous job done with smem stages + sBias
        if (tid < 128) { int vg = n0 + tid; sBias[tid] = (vg < Nn) ? bias[vg] : 0.f; }

        auto issue = [&](int kt, int sb) {
            int k0 = kt * 64;
            uint32_t sA = sbase + (uint32_t)sb * H2_STAGE;
            uint32_t sB = sA + BM * ROWH;
#pragma unroll
            for (int i = 0; i < 4; ++i) {
                int t = tid + i * NTHREADS;
                int row = t >> 3, ch = t & 7;
                int kg = k0 + ch * 8;
                cpa16(sA + row * ROWH + ch * 16, A + (size_t)(m0 + row) * lda + kg, 16);
            }
#pragma unroll
            for (int i = 0; i < 4; ++i) {
                int t = tid + i * NTHREADS;
                int row = t >> 3, ch = t & 7;
                int kg = k0 + ch * 8;
                int vg = n0 + row;
                bool ok = (vg < Nn);
                cpa16(sB + row * ROWH + ch * 16, B + (size_t)(ok ? vg : 0) * K + kg, ok ? 16 : 0);
            }
        };

        float c[2][8][4];
#pragma unroll
        for (int mt = 0; mt < 2; ++mt)
#pragma unroll
            for (int nt = 0; nt < 8; ++nt)
#pragma unroll
                for (int j = 0; j < 4; ++j) c[mt][nt][j] = 0.f;

        issue(0, 0);
        asm volatile("cp.async.commit_group;\n");
        issue(1, 1);
        asm volatile("cp.async.commit_group;\n");

        int sIssue = 2, sComp = 0;
        for (int it = 0; it < ntiles; ++it) {
            asm volatile("cp.async.wait_group 1;\n");
            __syncthreads();
            int nt_tile = it + 2;
            if (nt_tile < ntiles) issue(nt_tile, sIssue);
            sIssue = (sIssue == 2) ? 0 : sIssue + 1;
            asm volatile("cp.async.commit_group;\n");

            uint32_t so = (uint32_t)sComp * H2_STAGE;
            sComp = (sComp == 2) ? 0 : sComp + 1;
#pragma unroll
            for (int kk = 0; kk < 4; ++kk) {
                uint32_t a[2][4], b[4][4];
                ldsm4(a[0][0], a[0][1], a[0][2], a[0][3], aAddr[0] + so + kk * 32);
                ldsm4(a[1][0], a[1][1], a[1][2], a[1][3], aAddr[1] + so + kk * 32);
#pragma unroll
                for (int np = 0; np < 4; ++np)
                    ldsm4(b[np][0], b[np][1], b[np][2], b[np][3], bAddr[np] + so + kk * 32);
#pragma unroll
                for (int mt = 0; mt < 2; ++mt)
#pragma unroll
                    for (int nt = 0; nt < 8; ++nt)
                        mma16816(c[mt][nt], a[mt], b[nt >> 1][(nt & 1) * 2],
                                 b[nt >> 1][(nt & 1) * 2 + 1]);
            }
        }

        const bool edge = (n0 + 128 > Nn);
#pragma unroll
        for (int mt = 0; mt < 2; ++mt) {
#pragma unroll
            for (int half = 0; half < 2; ++half) {
                int rloc = warp_m * 32 + mt * 16 + gid + half * 8;
                int row = m0 + rloc;
                int tv = sTgt[rloc];
                int tcol = (tv < 19997) ? tv - n0 : -1000000;
                float s2 = 0.f;
                if (!edge) {
#pragma unroll
                    for (int nt = 0; nt < 8; ++nt) {
#pragma unroll
                        for (int jj = 0; jj < 2; ++jj) {
                            int nloc = warp_n * 64 + nt * 8 + tg * 2 + jj;
                            float logit = c[mt][nt][half * 2 + jj] + sBias[nloc];
                            s2 += __expf(logit);
                            if (nloc == tcol) g_tgtLogit[row] = logit;
                        }
                    }
                } else {
#pragma unroll
                    for (int nt = 0; nt < 8; ++nt) {
#pragma unroll
                        for (int jj = 0; jj < 2; ++jj) {
                            int nloc = warp_n * 64 + nt * 8 + tg * 2 + jj;
                            float logit = c[mt][nt][half * 2 + jj] + sBias[nloc];
                            if (n0 + nloc < Nn) {
                                s2 += __expf(logit);
                                if (nloc == tcol) g_tgtLogit[row] = logit;
                                if (n0 + nloc >= Nn - 3)
                                    g_clLogit[row * 3 + (n0 + nloc - (Nn - 3))] = logit;
                            }
                        }
                    }
                }
                s2 += __shfl_xor_sync(0xffffffffu, s2, 1);
                s2 += __shfl_xor_sync(0xffffffffu, s2, 2);
                if (tg == 0) sSum[rloc * 2 + warp_n] += s2;
            }
        }
    }

    // single flush
    __syncthreads();
    if (tid < 128)
        atomicAdd(&g_sumExp[m0 + tid], sSum[tid * 2] + sSum[tid * 2 + 1]);
}

// ================= streaming tail logits GEMM (CB = B chunk K-width) =================
template <int KV, int TPC, int CB>
__global__ __launch_bounds__(NTHREADS, 2)
void tail_kernel(const float* __restrict__ bias, int Koff, int Boff, int Nn,
                 int ytiles, int cut_l, float* __restrict__ sumExp) {
    constexpr int K_pad = (KV < 32) ? 32 : KV;
    constexpr int CH    = K_pad / 8;
    constexpr int ROWA  = K_pad * 2 + 16;
    constexpr int CEFF  = (KV < CB) ? KV : CB;
    constexpr int CKS   = CEFF / 16;
    constexpr int NT_K  = (KV > CB) ? KV / CB : 1;
    constexpr int ROWBT = CB * 2 + 16;
    constexpr int BSTG  = 128 * ROWBT;
    constexpr bool AREG = (KV <= 64);
    constexpr int NKS   = KV / 16;
    constexpr int BOFF  = BM * ROWA;
    constexpr int BIASOFF = BOFF + 3 * BSTG;
    constexpr int TGTOFF  = BIASOFF + 3 * 512;
    constexpr int SSUMOFF = TGTOFF + 512;
    constexpr int CPR   = CB / 8;
    constexpr int RPP   = NTHREADS / CPR;
    constexpr int NPASS = 128 / RPP;

    extern __shared__ __align__(16) char smem[];
    uint32_t sbase = (uint32_t)__cvta_generic_to_shared(smem);
    int* sTgt = (int*)(smem + TGTOFF);
    float* sSum = (float*)(smem + SSUMOFF);   // [128][2]

    const int tid = threadIdx.x;
    const int lane = tid & 31, wid = tid >> 5;
    const int gid = lane >> 2, tg = lane & 3;
    const int warp_m = wid >> 1, warp_n = wid & 1;
    const int m0 = blockIdx.x * BM;
    const int t0 = blockIdx.y * TPC;
    const int ntl = (ytiles - t0 < TPC) ? (ytiles - t0) : TPC;
    const int QTOT = ntl * NT_K;

    const __nv_bfloat16* A = g_proj + Koff;
    const __nv_bfloat16* B = g_Wb + Boff;
    const int lda = 1360;

    if (tid < BM) sTgt[tid] = g_target[m0 + tid];
    if (tid < 256) sSum[tid] = 0.f;

    for (int i = tid; i < BM * CH; i += NTHREADS) {
        int row = i / CH, ch = i - row * CH;
        int kg = ch * 8;
        cpa16(sbase + row * ROWA + ch * 16, A + (size_t)(m0 + row) * lda + kg,
              (kg < KV) ? 16 : 0);
    }
    asm volatile("cp.async.commit_group;\n");

    const int chB = tid % CPR;
    const int rB0 = tid / CPR;

    auto issueB = [&](int q, int sb) {
        int tile = q / NT_K;
        int kt = q - tile * NT_K;
        int n0 = (t0 + tile) * 128;
        int kg = kt * CB + chB * 8;
        uint32_t sB = sbase + BOFF + (uint32_t)sb * BSTG;
#pragma unroll
        for (int it = 0; it < NPASS; ++it) {
            int row = rB0 + it * RPP;
            int vg = n0 + row;
            bool ok = (vg < Nn) && (kg < KV);
            cpa16(sB + row * ROWBT + chB * 16, B + (size_t)(ok ? vg : 0) * KV + (ok ? kg : 0),
                  ok ? 16 : 0);
        }
        if (kt == 0 && tid < 32) {
            int off = n0 + tid * 4;
            int rem = Nn - off;
            int bytes = (rem >= 4) ? 16 : ((rem > 0) ? rem * 4 : 0);
            cpa16(sbase + BIASOFF + sb * 512 + tid * 16,
                  bias + ((rem > 0) ? off : 0), bytes);
        }
    };

    issueB(0, 0);
    asm volatile("cp.async.commit_group;\n");
    if (1 < QTOT) issueB(1, 1);
    asm volatile("cp.async.commit_group;\n");

    const int li = lane & 7, lq = lane >> 3;
    uint32_t aAddr[2], bOffu[4];
#pragma unroll
    for (int mt = 0; mt < 2; ++mt) {
        int row = warp_m * 32 + mt * 16 + (lq & 1) * 8 + li;
        aAddr[mt] = sbase + row * ROWA + ((lq >> 1) * 8) * 2;
    }
#pragma unroll
    for (int np = 0; np < 4; ++np) {
        int row = warp_n * 64 + np * 16 + (lq >> 1) * 8 + li;
        bOffu[np] = sbase + BOFF + row * ROWBT + ((lq & 1) * 8) * 2;
    }

    asm volatile("cp.async.wait_group 2;\n");
    __syncthreads();

    uint32_t aF[2][AREG ? NKS : 1][4];
    if constexpr (AREG) {
#pragma unroll
        for (int ks = 0; ks < NKS; ++ks) {
            ldsm4(aF[0][ks][0], aF[0][ks][1], aF[0][ks][2], aF[0][ks][3], aAddr[0] + ks * 32);
            ldsm4(aF[1][ks][0], aF[1][ks][1], aF[1][ks][2], aF[1][ks][3], aAddr[1] + ks * 32);
        }
    }

    float c[2][8][4];
#pragma unroll
    for (int mt = 0; mt < 2; ++mt)
#pragma unroll
        for (int nt = 0; nt < 8; ++nt)
#pragma unroll
            for (int j = 0; j < 4; ++j) c[mt][nt][j] = 0.f;

    int sIssue = 2, sComp = 0, sBiasStage = 0;
    int kt = 0, tile = 0;
    for (int q = 0; q < QTOT; ++q) {
        asm volatile("cp.async.wait_group 1;\n");
        __syncthreads();
        if (q + 2 < QTOT) issueB(q + 2, sIssue);
        sIssue = (sIssue == 2) ? 0 : sIssue + 1;
        asm volatile("cp.async.commit_group;\n");

#pragma unroll
        for (int kk = 0; kk < CKS; ++kk) {
            uint32_t b[4][4];
#pragma unroll
            for (int np = 0; np < 4; ++np)
                ldsm4(b[np][0], b[np][1], b[np][2], b[np][3],
                      bOffu[np] + (uint32_t)sComp * BSTG + kk * 32);
            const uint32_t* a0;
            const uint32_t* a1;
            uint32_t at[2][4];
            if constexpr (AREG) {
                a0 = aF[0][kt * CKS + kk];
                a1 = aF[1][kt * CKS + kk];
            } else {
                ldsm4(at[0][0], at[0][1], at[0][2], at[0][3], aAddr[0] + (kt * CKS + kk) * 32);
                ldsm4(at[1][0], at[1][1], at[1][2], at[1][3], aAddr[1] + (kt * CKS + kk) * 32);
                a0 = at[0]; a1 = at[1];
            }
#pragma unroll
            for (int nt = 0; nt < 8; ++nt) {
                mma16816(c[0][nt], a0, b[nt >> 1][(nt & 1) * 2], b[nt >> 1][(nt & 1) * 2 + 1]);
                mma16816(c[1][nt], a1, b[nt >> 1][(nt & 1) * 2], b[nt >> 1][(nt & 1) * 2 + 1]);
            }
        }
        sComp = (sComp == 2) ? 0 : sComp + 1;

        if (++kt == NT_K) {
            kt = 0;
            int n0 = (t0 + tile) * 128;
            const float* sBias = (const float*)(smem + BIASOFF + sBiasStage * 512);
            const bool edge = (n0 + 128 > Nn);
#pragma unroll
            for (int mt = 0; mt < 2; ++mt) {
#pragma unroll
                for (int half = 0; half < 2; ++half) {
                    int rloc = warp_m * 32 + mt * 16 + gid + half * 8;
                    int row = m0 + rloc;
                    int tcol = sTgt[rloc] - cut_l - n0;
                    float s2 = 0.f;
                    if (!edge) {
#pragma unroll
                        for (int nt = 0; nt < 8; ++nt) {
#pragma unroll
                            for (int jj = 0; jj < 2; ++jj) {
                                int nloc = warp_n * 64 + nt * 8 + tg * 2 + jj;
                                float logit = c[mt][nt][half * 2 + jj] + sBias[nloc];
                                s2 += __expf(logit);
                                if (nloc == tcol) g_tgtLogit[row] = logit;
                            }
                        }
                    } else {
#pragma unroll
                        for (int nt = 0; nt < 8; ++nt) {
#pragma unroll
                            for (int jj = 0; jj < 2; ++jj) {
                                int nloc = warp_n * 64 + nt * 8 + tg * 2 + jj;
                                float logit = c[mt][nt][half * 2 + jj] + sBias[nloc];
                                if (n0 + nloc < Nn) {
                                    s2 += __expf(logit);
                                    if (nloc == tcol) g_tgtLogit[row] = logit;
                                }
                            }
                        }
                    }
                    s2 += __shfl_xor_sync(0xffffffffu, s2, 1);
                    s2 += __shfl_xor_sync(0xffffffffu, s2, 2);
                    if (tg == 0) sSum[rloc * 2 + warp_n] += s2;
                }
            }
#pragma unroll
            for (int mt = 0; mt < 2; ++mt)
#pragma unroll
                for (int nt = 0; nt < 8; ++nt)
#pragma unroll
                    for (int j = 0; j < 4; ++j) c[mt][nt][j] = 0.f;
            ++tile;
            int qn = q + 1;
            sBiasStage = qn - (qn / 3) * 3;
        }
    }

    // single flush
    __syncthreads();
    if (tid < 128)
        atomicAdd(&sumExp[m0 + tid], sSum[tid * 2] + sSum[tid * 2 + 1]);
}

// ---------------- final NLL ----------------
__global__ void final_kernel(float* __restrict__ out) {
    int n = blockIdx.x * blockDim.x + threadIdx.x;
    if (n >= 1024) return;
    int t = g_target[n];
    int c = (t < 19997) ? 0 : (t < 39997) ? 1 : (t < 199997) ? 2 : 3;
    float head_lse = logf(g_sumExp[n]);
    float nll;
    if (c == 0) {
        nll = head_lse - g_tgtLogit[n];
    } else {
        float tail_lse = logf(g_sumExp[c * 1024 + n]);
        nll = head_lse - g_clLogit[n * 3 + (c - 1)] + tail_lse - g_tgtLogit[n];
    }
    out[n] = nll;
}

// ---------------- launch ----------------
extern "C" void kernel_launch(void* const* d_in, const int* in_sizes, int n_in,
                              void* d_out, int out_size) {
    const float* hidden = (const float*)d_in[0];
    const void*  target = (const void*)d_in[1];
    const float* W0 = (const float*)d_in[2];
    const float* b0 = (const float*)d_in[3];
    const float* p0 = (const float*)d_in[4];
    const float* W1 = (const float*)d_in[5];
    const float* b1 = (const float*)d_in[6];
    const float* p1 = (const float*)d_in[7];
    const float* W2 = (const float*)d_in[8];
    const float* b2 = (const float*)d_in[9];
    const float* p2 = (const float*)d_in[10];
    const float* W3 = (const float*)d_in[11];
    const float* b3 = (const float*)d_in[12];
    const float* p3 = (const float*)d_in[13];
    const float* cw = (const float*)d_in[14];
    const float* cb = (const float*)d_in[15];
    float* out = (float*)d_out;

    // tail smem: A + 3*B + bias + tgt + sSum(1024)
    const int S_T1 = 128 * 528 + 3 * (128 * 80)  + 3 * 512 + 512 + 1024;  // KV=256,CB=32
    const int S_T2 = 128 * 144 + 3 * (128 * 144) + 3 * 512 + 512 + 1024;  // KV=64, CB=64
    const int S_T3 = 128 * 80  + 3 * (128 * 80)  + 3 * 512 + 512 + 1024;  // KV=16, CB=32

    static cudaStream_t s1 = nullptr;
    static cudaEvent_t r0, eWH, eW;
    if (!s1) {
        cudaStreamCreateWithFlags(&s1, cudaStreamNonBlocking);
        cudaEventCreateWithFlags(&r0, cudaEventDisableTiming);
        cudaEventCreateWithFlags(&eWH, cudaEventDisableTiming);
        cudaEventCreateWithFlags(&eW, cudaEventDisableTiming);
        cudaFuncSetAttribute(proj_kernel, cudaFuncAttributeMaxDynamicSharedMemorySize, PROJ_SMEM);
        cudaFuncSetAttribute(head_kernel, cudaFuncAttributeMaxDynamicSharedMemorySize, H2_SMEM);
        cudaFuncSetAttribute(tail_kernel<256, 5, 32>, cudaFuncAttributeMaxDynamicSharedMemorySize, S_T1);
        cudaFuncSetAttribute(tail_kernel<64, 17, 64>, cudaFuncAttributeMaxDynamicSharedMemorySize, S_T2);
        cudaFuncSetAttribute(tail_kernel<16, 16, 32>, cudaFuncAttributeMaxDynamicSharedMemorySize, S_T3);
    }

    __nv_bfloat16 *dh, *dpT, *dproj;
    float *dsum, *dbh;
    cudaGetSymbolAddress((void**)&dh, g_hidden);
    cudaGetSymbolAddress((void**)&dpT, g_pT);
    cudaGetSymbolAddress((void**)&dproj, g_proj);
    cudaGetSymbolAddress((void**)&dsum, g_sumExp);
    cudaGetSymbolAddress((void**)&dbh, g_biasHead);

    // side stream: decode + head-W convert (eWH), then tail-W convert (eW)
    cudaEventRecord(r0, 0);
    cudaStreamWaitEvent(s1, r0, 0);
    decode_targets_kernel<<<1, 256, 0, s1>>>(target, 1024);
    prep_w_head_kernel<<<2048, 256, 0, s1>>>(W0, cw, b0, cb);
    cudaEventRecord(eWH, s1);
    prep_w_tail_kernel<<<2048, 256, 0, s1>>>(W1, W2, W3);
    cudaEventRecord(eW, s1);

    prep_light_kernel<<<1024, 256>>>(hidden, p0, p1, p2, p3);
    proj_kernel<<<dim3(8, 11), NTHREADS, PROJ_SMEM>>>(dh, dpT, 1360, dproj, 1360);

    // head starts as soon as W0 is converted; tails wait for the rest
    cudaStreamWaitEvent(0, eWH, 0);
    head_kernel<<<HEAD_GRID, NTHREADS, H2_SMEM>>>(dbh);
    cudaStreamWaitEvent(0, eW, 0);
    tail_kernel<64, 17, 64><<<dim3(8, 74), NTHREADS, S_T2>>>(
        b2, 1280, 25600000, 160000, 1250, 39997, dsum + 2048);
    tail_kernel<16, 16, 32><<<dim3(8, 34), NTHREADS, S_T3>>>(
        b3, 1344, 35840000, 67738, 530, 199997, dsum + 3072);
    tail_kernel<256, 5, 32><<<dim3(8, 32), NTHREADS, S_T1>>>(
        b1, 1024, 20480000, 20000, 157, 19997, dsum + 1024);

    final_kernel<<<4, 256>>>(out);
}